// round 1
// baseline (speedup 1.0000x reference)
#include <cuda_runtime.h>

#define HID 128
#define NA  1024
#define NR  1024

// Scratch: PA (with bs1 folded in) and PR, row-major [row][h]
__device__ float g_PA[NA * HID];
__device__ float g_PR[NR * HID];

// ---------------------------------------------------------------------------
// Kernel 1: per-row fused MLP chain + score projection.
// Block = 1 row (agents: blockIdx < 1024, regions: >= 1024), 128 threads,
// thread j owns output column j of every layer.
// ---------------------------------------------------------------------------
__global__ __launch_bounds__(128) void embed_kernel(
    const float* __restrict__ xa,  const float* __restrict__ xr,
    const float* __restrict__ Wa1, const float* __restrict__ ba1,
    const float* __restrict__ Wa2, const float* __restrict__ ba2,
    const float* __restrict__ Wr1, const float* __restrict__ br1,
    const float* __restrict__ Wr2, const float* __restrict__ br2,
    const float* __restrict__ Ws1, const float* __restrict__ bs1)
{
    int row = blockIdx.x;
    bool agent = row < NA;
    int r = agent ? row : row - NA;
    int idim = agent ? 24 : 20;
    const float* x  = agent ? (xa + r * 24) : (xr + r * 20);
    const float* W1 = agent ? Wa1 : Wr1;
    const float* b1 = agent ? ba1 : br1;
    const float* W2 = agent ? Wa2 : Wr2;
    const float* b2 = agent ? ba2 : br2;
    const float* Ws = agent ? Ws1 : (Ws1 + HID * HID);  // Ws1_a / Ws1_r
    float* outp = agent ? g_PA : g_PR;

    __shared__ __align__(16) float xs[24];
    __shared__ __align__(16) float h1[HID];
    __shared__ __align__(16) float h2[HID];

    int j = threadIdx.x;
    if (j < idim) xs[j] = x[j];
    __syncthreads();

    // Layer 1
    float acc = b1[j];
    for (int k = 0; k < idim; ++k)
        acc = fmaf(xs[k], W1[k * HID + j], acc);
    h1[j] = fmaxf(acc, 0.f);
    __syncthreads();

    // Layer 2 (4 partial accumulators, float4 smem reads)
    float a0 = 0.f, a1 = 0.f, a2 = 0.f, a3 = 0.f;
    #pragma unroll
    for (int k4 = 0; k4 < HID / 4; ++k4) {
        float4 h = *(const float4*)&h1[k4 * 4];
        a0 = fmaf(h.x, W2[(k4 * 4 + 0) * HID + j], a0);
        a1 = fmaf(h.y, W2[(k4 * 4 + 1) * HID + j], a1);
        a2 = fmaf(h.z, W2[(k4 * 4 + 2) * HID + j], a2);
        a3 = fmaf(h.w, W2[(k4 * 4 + 3) * HID + j], a3);
    }
    h2[j] = fmaxf((a0 + a1) + (a2 + a3) + b2[j], 0.f);
    __syncthreads();

    // Score projection (pa / pr); fold bs1 into PA only.
    a0 = a1 = a2 = a3 = 0.f;
    #pragma unroll
    for (int k4 = 0; k4 < HID / 4; ++k4) {
        float4 h = *(const float4*)&h2[k4 * 4];
        a0 = fmaf(h.x, Ws[(k4 * 4 + 0) * HID + j], a0);
        a1 = fmaf(h.y, Ws[(k4 * 4 + 1) * HID + j], a1);
        a2 = fmaf(h.z, Ws[(k4 * 4 + 2) * HID + j], a2);
        a3 = fmaf(h.w, Ws[(k4 * 4 + 3) * HID + j], a3);
    }
    float pv = (a0 + a1) + (a2 + a3);
    if (agent) pv += bs1[j];
    outp[r * HID + j] = pv;
}

// ---------------------------------------------------------------------------
// Kernel 2: pairwise scores.
// Block tile: 64 agents x 64 regions, 256 threads (16x16), 4x4 per thread.
// Smem tiles stored transposed [h_local][col] with XOR-(h>>2) swizzle on the
// 16B group index: conflict-free float4 compute loads, ~2-way STS on fill.
// h processed in two chunks of 64 to stay within 48KB static smem.
// ---------------------------------------------------------------------------
__global__ __launch_bounds__(256) void pair_kernel(
    const float* __restrict__ Ws2, const float* __restrict__ bs2,
    float* __restrict__ out)
{
    __shared__ __align__(16) float As[64 * 64];
    __shared__ __align__(16) float Rs[64 * 64];
    __shared__ __align__(16) float ws[HID];

    int t  = threadIdx.x;
    int tx = t & 15;        // region group (4 regions)
    int ty = t >> 4;        // agent group (4 agents)
    int a0 = blockIdx.y * 64;
    int r0 = blockIdx.x * 64;

    if (t < HID) ws[t] = Ws2[t];

    float acc[4][4];
    #pragma unroll
    for (int i = 0; i < 4; ++i)
        #pragma unroll
        for (int jj = 0; jj < 4; ++jj) acc[i][jj] = 0.f;

    int hqf = t & 15;   // fill: h-quad index (coalesced gmem reads)
    int ab  = t >> 4;   // fill: column base

    for (int chunk = 0; chunk < 2; ++chunk) {
        int hb = chunk * 64;
        __syncthreads();   // protect previous chunk's reads (and ws on chunk 0)

        // Fill both tiles, transposing [row][h] -> [h_local][col] w/ swizzle.
        #pragma unroll
        for (int it = 0; it < 4; ++it) {
            int a   = ab + it * 16;                       // 0..63
            int col = ((((a >> 2) ^ hqf) << 2)) | (a & 3); // swizzled column
            float4 va = *(const float4*)&g_PA[(size_t)(a0 + a) * HID + hb + hqf * 4];
            As[(hqf * 4 + 0) * 64 + col] = va.x;
            As[(hqf * 4 + 1) * 64 + col] = va.y;
            As[(hqf * 4 + 2) * 64 + col] = va.z;
            As[(hqf * 4 + 3) * 64 + col] = va.w;
            float4 vr = *(const float4*)&g_PR[(size_t)(r0 + a) * HID + hb + hqf * 4];
            Rs[(hqf * 4 + 0) * 64 + col] = vr.x;
            Rs[(hqf * 4 + 1) * 64 + col] = vr.y;
            Rs[(hqf * 4 + 2) * 64 + col] = vr.z;
            Rs[(hqf * 4 + 3) * 64 + col] = vr.w;
        }
        __syncthreads();

        // Compute: 64 h values in quads.
        #pragma unroll 4
        for (int hq = 0; hq < 16; ++hq) {
            float4 w4 = *(const float4*)&ws[hb + hq * 4];
            int cA = (ty ^ hq) << 2;
            int cR = (tx ^ hq) << 2;
            #pragma unroll
            for (int i = 0; i < 4; ++i) {
                float4 av = *(const float4*)&As[(hq * 4 + i) * 64 + cA];
                float4 rv = *(const float4*)&Rs[(hq * 4 + i) * 64 + cR];
                float w = (i == 0) ? w4.x : (i == 1) ? w4.y : (i == 2) ? w4.z : w4.w;
                float pav[4] = {av.x, av.y, av.z, av.w};
                float prv[4] = {rv.x, rv.y, rv.z, rv.w};
                #pragma unroll
                for (int ii = 0; ii < 4; ++ii)
                    #pragma unroll
                    for (int jj = 0; jj < 4; ++jj)
                        acc[ii][jj] = fmaf(fmaxf(pav[ii] + prv[jj], 0.f), w, acc[ii][jj]);
            }
        }
    }

    float b = *bs2;
    #pragma unroll
    for (int ii = 0; ii < 4; ++ii) {
        int a = a0 + ty * 4 + ii;
        float4 o = make_float4(acc[ii][0] + b, acc[ii][1] + b,
                               acc[ii][2] + b, acc[ii][3] + b);
        *(float4*)&out[(size_t)a * NR + r0 + tx * 4] = o;
    }
}

// ---------------------------------------------------------------------------
extern "C" void kernel_launch(void* const* d_in, const int* in_sizes, int n_in,
                              void* d_out, int out_size)
{
    const float* xa  = (const float*)d_in[0];
    const float* xr  = (const float*)d_in[1];
    const float* Wa1 = (const float*)d_in[2];
    const float* ba1 = (const float*)d_in[3];
    const float* Wa2 = (const float*)d_in[4];
    const float* ba2 = (const float*)d_in[5];
    const float* Wr1 = (const float*)d_in[6];
    const float* br1 = (const float*)d_in[7];
    const float* Wr2 = (const float*)d_in[8];
    const float* br2 = (const float*)d_in[9];
    const float* Ws1 = (const float*)d_in[10];
    const float* bs1 = (const float*)d_in[11];
    const float* Ws2 = (const float*)d_in[12];
    const float* bs2 = (const float*)d_in[13];
    float* out = (float*)d_out;

    embed_kernel<<<NA + NR, 128>>>(xa, xr, Wa1, ba1, Wa2, ba2,
                                   Wr1, br1, Wr2, br2, Ws1, bs1);
    pair_kernel<<<dim3(NR / 64, NA / 64), 256>>>(Ws2, bs2, out);
}